// round 8
// baseline (speedup 1.0000x reference)
#include <cuda_runtime.h>
#include <cuda_fp16.h>
#include <cstdint>

#define N_ROWS 8192
#define K_DIM  512
#define J_DIM  256
#define KT     32
#define KITERS 16

// ---------------- device scratch ----------------
__device__ __half g_B[2][2][J_DIM][K_DIM];   // [mat][hi/lo][n][k], 1MB
__device__ float  g_part[2][N_ROWS];

// ---------------- smem layout (bytes) ----------------
// B: 2 stages x [mat*2+hilo][n 128][80B] = 2 x 40960 = 81920
// ARAW: single stage [mat][row 64][160B] = 20480 @ 81920
#define ARAW   81920
#define SMEM_SIZE 102400
#define EPI_STRIDE 136            // floats
#define EPI_E_OFF  34816          // bytes = 64*136*4

// ---------------- helpers ----------------
__device__ __forceinline__ uint32_t smem_u32(const void* p) {
    uint32_t a;
    asm("{ .reg .u64 t; cvta.to.shared.u64 t, %1; cvt.u32.u64 %0, t; }" : "=r"(a) : "l"(p));
    return a;
}
__device__ __forceinline__ void cp16(uint32_t sdst, const void* g) {
    asm volatile("cp.async.cg.shared.global [%0], [%1], 16;" :: "r"(sdst), "l"(g));
}
__device__ __forceinline__ void cp_commit() { asm volatile("cp.async.commit_group;"); }
__device__ __forceinline__ void cp_wait0()  { asm volatile("cp.async.wait_group 0;"); }

__device__ __forceinline__ void ldsm4(uint32_t (&r)[4], uint32_t addr) {
    asm volatile("ldmatrix.sync.aligned.m8n8.x4.shared.b16 {%0,%1,%2,%3}, [%4];"
        : "=r"(r[0]), "=r"(r[1]), "=r"(r[2]), "=r"(r[3]) : "r"(addr));
}
__device__ __forceinline__ void mma16816(float (&c)[4], const uint32_t (&a)[4],
                                         uint32_t b0, uint32_t b1) {
    asm volatile("mma.sync.aligned.m16n8k16.row.col.f32.f16.f16.f32 "
        "{%0,%1,%2,%3}, {%4,%5,%6,%7}, {%8,%9}, {%0,%1,%2,%3};"
        : "+f"(c[0]), "+f"(c[1]), "+f"(c[2]), "+f"(c[3])
        : "r"(a[0]), "r"(a[1]), "r"(a[2]), "r"(a[3]), "r"(b0), "r"(b1));
}
__device__ __forceinline__ uint32_t packh2(__half a, __half b) {
    __half2 h = __halves2half2(a, b);
    return *reinterpret_cast<uint32_t*>(&h);
}
__device__ __forceinline__ void split(float x, __half& hi, __half& lo) {
    hi = __float2half_rn(x);
    lo = __float2half_rn(x - __half2float(hi));
}
// split a float2 into packed hi-half2 and lo-half2
__device__ __forceinline__ void split2(float2 v, uint32_t& h, uint32_t& l) {
    __half hx, lx, hy, ly;
    split(v.x, hx, lx);
    split(v.y, hy, ly);
    h = packh2(hx, hy);
    l = packh2(lx, ly);
}

// ============ prep: W[512][256] -> g_B[mat][hi/lo][n][k] fp16 ============
__global__ void __launch_bounds__(256)
prep_kernel(const float* __restrict__ Wu, const float* __restrict__ We)
{
    __shared__ float s[16][68];
    const int bid = blockIdx.x;
    const int m   = bid >> 7;
    const int kc  = (bid >> 2) & 31;
    const int nc  = bid & 3;
    const int k0  = kc * 16, n0 = nc * 64;
    const float* W = m ? We : Wu;
    const int tid = threadIdx.x;

    {
        const int kk = tid >> 4, n4 = (tid & 15) * 4;
        *reinterpret_cast<float4*>(&s[kk][n4]) =
            *reinterpret_cast<const float4*>(&W[(size_t)(k0 + kk) * J_DIM + n0 + n4]);
    }
    __syncthreads();

    #pragma unroll
    for (int i = 0; i < 2; ++i) {
        const int o = tid + i * 256;
        const int n = o >> 3, q = o & 7;
        const float x0 = s[2 * q][n];
        const float x1 = s[2 * q + 1][n];
        __half h0, l0, h1, l1;
        split(x0, h0, l0);
        split(x1, h1, l1);
        *reinterpret_cast<uint32_t*>(&g_B[m][0][n0 + n][k0 + 2 * q]) = packh2(h0, h1);
        *reinterpret_cast<uint32_t*>(&g_B[m][1][n0 + n][k0 + 2 * q]) = packh2(l0, l1);
    }
}

// ============ GEMM: 256 CTAs (mtile 128 x ntile 2), 64 rows x 128 cols ============
__global__ void __launch_bounds__(256, 2)
gemm_kernel(const float* __restrict__ user, const float* __restrict__ event,
            const float* __restrict__ bu, const float* __restrict__ be)
{
    extern __shared__ __align__(1024) char smem[];
    const uint32_t sb = smem_u32(smem);
    const int tid  = threadIdx.x;
    const int wid  = tid >> 5;
    const int lane = tid & 31;

    const int mtile = blockIdx.x >> 1;
    const int ntile = blockIdx.x & 1;
    const int m0 = mtile * 64;
    const int n0 = ntile * 128;

    const char* bflat = reinterpret_cast<const char*>(&g_B[0][0][0][0]);

    // A cp.async mapping: 4 chunks/thread
    // e = tid + i*256: mat = e>>9, row = (e&511)>>3, q = e&7
    // B cp.async mapping: 8 chunks/thread: c = tid+i*256, nrow = c>>2, q = c&3

    // ---- prologue: issue A(0), B(0) ----
    #pragma unroll
    for (int i = 0; i < 4; ++i) {
        const int e = tid + i * 256;
        const int mat = e >> 9, rem = e & 511, row = rem >> 3, q = rem & 7;
        cp16(sb + ARAW + mat * 10240 + row * 160 + q * 16,
             (mat ? event : user) + (size_t)(m0 + row) * K_DIM + 0 * KT + q * 4);
    }
    #pragma unroll
    for (int i = 0; i < 8; ++i) {
        const int c = tid + i * 256;
        const int nrow = c >> 2, q = c & 3;
        const int mat = nrow >> 8, h = (nrow >> 7) & 1, n = nrow & 127;
        cp16(sb + 0 * 40960 + nrow * 80 + q * 16,
             bflat + (((size_t)(mat * 2 + h) * J_DIM + n0 + n) * K_DIM + 0 * KT) * 2 + q * 16);
    }
    cp_commit();

    // warp roles: g = mat, wm = 32-row half, wn = 64-col half
    const int g  = wid >> 2;
    const int wm = (wid >> 1) & 1;
    const int wn = wid & 1;
    // A lds base for this lane's low row: row = wm*32 + (lane>>2), col offset (lane&3)*2
    const uint32_t a_lds = sb + ARAW + g * 10240
                         + (uint32_t)((wm * 32 + (lane >> 2)) * 160 + (lane & 3) * 8);
    const uint32_t b_off = (uint32_t)((wn * 64 + (lane & 7) + ((lane >> 4) & 1) * 8) * 80
                                      + ((lane >> 3) & 1) * 16);

    float acc[2][8][4];
    #pragma unroll
    for (int mt = 0; mt < 2; ++mt)
        #pragma unroll
        for (int no = 0; no < 8; ++no)
            #pragma unroll
            for (int x = 0; x < 4; ++x) acc[mt][no][x] = 0.f;

    for (int t = 0; t < KITERS; ++t) {
        const int s = t & 1;

        cp_wait0();
        __syncthreads();                    // A(t), B(t) resident + visible

        // ---- extract A fragments to regs (hi/lo) ----
        // frag regs: ah[mt][ks][4], al[mt][ks][4]
        uint32_t ah[2][2][4], al[2][2][4];
        #pragma unroll
        for (int mt = 0; mt < 2; ++mt) {
            #pragma unroll
            for (int ks = 0; ks < 2; ++ks) {
                const uint32_t base = a_lds + (uint32_t)(ks * 64);  // ks*16 cols * 4B
                const float2 v0 = *reinterpret_cast<const float2*>(
                    (const char*)smem + (base - sb) + mt * 2560);            // (r0, c0)
                const float2 v1 = *reinterpret_cast<const float2*>(
                    (const char*)smem + (base - sb) + mt * 2560 + 8 * 160);  // (r0+8, c0)
                const float2 v2 = *reinterpret_cast<const float2*>(
                    (const char*)smem + (base - sb) + mt * 2560 + 32);       // (r0, c0+8)
                const float2 v3 = *reinterpret_cast<const float2*>(
                    (const char*)smem + (base - sb) + mt * 2560 + 8 * 160 + 32);
                split2(v0, ah[mt][ks][0], al[mt][ks][0]);
                split2(v1, ah[mt][ks][1], al[mt][ks][1]);
                split2(v2, ah[mt][ks][2], al[mt][ks][2]);
                split2(v3, ah[mt][ks][3], al[mt][ks][3]);
            }
        }
        __syncthreads();                    // A raw buffer free for next copy

        // ---- issue A(t+1), B(t+1) ----
        if (t + 1 < KITERS) {
            const int nt = t + 1, ns = s ^ 1;
            #pragma unroll
            for (int i = 0; i < 4; ++i) {
                const int e = tid + i * 256;
                const int mat = e >> 9, rem = e & 511, row = rem >> 3, q = rem & 7;
                cp16(sb + ARAW + mat * 10240 + row * 160 + q * 16,
                     (mat ? event : user) + (size_t)(m0 + row) * K_DIM + nt * KT + q * 4);
            }
            #pragma unroll
            for (int i = 0; i < 8; ++i) {
                const int c = tid + i * 256;
                const int nrow = c >> 2, q = c & 3;
                const int mat = nrow >> 8, h = (nrow >> 7) & 1, n = nrow & 127;
                cp16(sb + ns * 40960 + nrow * 80 + q * 16,
                     bflat + (((size_t)(mat * 2 + h) * J_DIM + n0 + n) * K_DIM + nt * KT) * 2
                           + q * 16);
            }
            cp_commit();
        }

        // ---- compute: pass-major, ng-pairs (acc reuse distance 8) ----
        const uint32_t bh_base = sb + s * 40960 + g * 20480;
        const uint32_t bl_base = bh_base + 10240;
        #pragma unroll
        for (int ks = 0; ks < 2; ++ks) {
            const uint32_t kb = ks * 32;
            #pragma unroll
            for (int ngp = 0; ngp < 2; ++ngp) {
                uint32_t bh[2][4], bl[2][4];
                #pragma unroll
                for (int j = 0; j < 2; ++j) {
                    const int ng = ngp * 2 + j;
                    ldsm4(bh[j], bh_base + b_off + ng * 1280 + kb);
                    ldsm4(bl[j], bl_base + b_off + ng * 1280 + kb);
                }
                // pass hh
                #pragma unroll
                for (int j = 0; j < 2; ++j) {
                    const int ng = ngp * 2 + j;
                    #pragma unroll
                    for (int mt = 0; mt < 2; ++mt) {
                        mma16816(acc[mt][2 * ng],     ah[mt][ks], bh[j][0], bh[j][1]);
                        mma16816(acc[mt][2 * ng + 1], ah[mt][ks], bh[j][2], bh[j][3]);
                    }
                }
                // pass hl
                #pragma unroll
                for (int j = 0; j < 2; ++j) {
                    const int ng = ngp * 2 + j;
                    #pragma unroll
                    for (int mt = 0; mt < 2; ++mt) {
                        mma16816(acc[mt][2 * ng],     ah[mt][ks], bl[j][0], bl[j][1]);
                        mma16816(acc[mt][2 * ng + 1], ah[mt][ks], bl[j][2], bl[j][3]);
                    }
                }
                // pass lh
                #pragma unroll
                for (int j = 0; j < 2; ++j) {
                    const int ng = ngp * 2 + j;
                    #pragma unroll
                    for (int mt = 0; mt < 2; ++mt) {
                        mma16816(acc[mt][2 * ng],     al[mt][ks], bh[j][0], bh[j][1]);
                        mma16816(acc[mt][2 * ng + 1], al[mt][ks], bh[j][2], bh[j][3]);
                    }
                }
            }
        }
    }

    // ---- epilogue: stage 64x128 fp32 tiles (reuse B smem region) ----
    __syncthreads();
    float* ep = reinterpret_cast<float*>(smem + (g ? EPI_E_OFF : 0));
    #pragma unroll
    for (int mt = 0; mt < 2; ++mt) {
        #pragma unroll
        for (int no = 0; no < 8; ++no) {
            const int row = wm * 32 + mt * 16 + (lane >> 2);
            const int col = wn * 64 + no * 8 + (lane & 3) * 2;
            *reinterpret_cast<float2*>(&ep[row * EPI_STRIDE + col]) =
                make_float2(acc[mt][no][0], acc[mt][no][1]);
            *reinterpret_cast<float2*>(&ep[(row + 8) * EPI_STRIDE + col]) =
                make_float2(acc[mt][no][2], acc[mt][no][3]);
        }
    }
    __syncthreads();

    // ---- partial dot (with biases) over this CTA's 128 cols ----
    {
        const float* Us = reinterpret_cast<const float*>(smem);
        const float* Es = reinterpret_cast<const float*>(smem + EPI_E_OFF);
        const int row = tid >> 2;
        const int t4  = tid & 3;
        float ssum = 0.f;
        #pragma unroll
        for (int j = 0; j < 8; ++j) {
            const int col = t4 * 32 + j * 4;
            const float4 u  = *reinterpret_cast<const float4*>(&Us[row * EPI_STRIDE + col]);
            const float4 e  = *reinterpret_cast<const float4*>(&Es[row * EPI_STRIDE + col]);
            const float4 b1 = *reinterpret_cast<const float4*>(&bu[n0 + col]);
            const float4 b2 = *reinterpret_cast<const float4*>(&be[n0 + col]);
            ssum += (u.x + b1.x) * (e.x + b2.x)
                  + (u.y + b1.y) * (e.y + b2.y)
                  + (u.z + b1.z) * (e.z + b2.z)
                  + (u.w + b1.w) * (e.w + b2.w);
        }
        ssum += __shfl_xor_sync(0xffffffffu, ssum, 1);
        ssum += __shfl_xor_sync(0xffffffffu, ssum, 2);
        if (t4 == 0)
            g_part[ntile][m0 + row] = ssum;
    }
}

// ============ combine ============
__global__ void __launch_bounds__(256)
combine_kernel(float* __restrict__ out)
{
    const int i = blockIdx.x * 256 + threadIdx.x;
    const float l = g_part[0][i] + g_part[1][i];
    out[i] = 1.0f / (1.0f + expf(-l));
}

extern "C" void kernel_launch(void* const* d_in, const int* in_sizes, int n_in,
                              void* d_out, int out_size)
{
    const float* user  = (const float*)d_in[0];
    const float* event = (const float*)d_in[1];
    const float* Wu    = (const float*)d_in[2];
    const float* bu    = (const float*)d_in[3];
    const float* We    = (const float*)d_in[4];
    const float* be    = (const float*)d_in[5];
    float* out = (float*)d_out;

    cudaFuncSetAttribute(gemm_kernel, cudaFuncAttributeMaxDynamicSharedMemorySize, SMEM_SIZE);

    prep_kernel<<<256, 256>>>(Wu, We);
    gemm_kernel<<<256, 256, SMEM_SIZE>>>(user, event, bu, be);
    combine_kernel<<<N_ROWS / 256, 256>>>(out);
}